// round 11
// baseline (speedup 1.0000x reference)
#include <cuda_runtime.h>
#include <cuda_bf16.h>
#include <cstdint>
#include <cstddef>

#define BB   2
#define TT   2048
#define CC   1024
#define DIM_ 1024
#define HH   16
#define HD_  64
#define M1   (BB*TT)        // 4096
#define N1   (3*DIM_)       // 3072
#define KDIM 1024
#define NROWS (BB*HH*TT)    // 65536

typedef __nv_bfloat16  bf16;
typedef __nv_bfloat162 bf162;

// ---------------------------------------------------------------------------
// Scratch — EXACTLY 64.5 MiB (proven footprint). No other globals.
// ---------------------------------------------------------------------------
__device__ __align__(16) bf16 g_qh[(size_t)NROWS*HD_], g_ql[(size_t)NROWS*HD_];
__device__ __align__(16) bf16 g_kh[(size_t)NROWS*HD_], g_kl[(size_t)NROWS*HD_];
__device__ __align__(16) bf16 g_vth[(size_t)NROWS*HD_], g_vtl[(size_t)NROWS*HD_];
__device__ float g_attn[(size_t)M1*DIM_];
__device__ float g_qn[NROWS], g_kn[NROWS];

// ---------------------------------------------------------------------------
// Helpers
// ---------------------------------------------------------------------------
__device__ __forceinline__ void bsplit(float x, bf16 &h, bf16 &l) {
    h = __float2bfloat16_rn(x);
    l = __float2bfloat16_rn(x - __bfloat162float(h));
}
__device__ __forceinline__ unsigned packb(bf16 a, bf16 b) {
    bf162 t; t.x = a; t.y = b;
    return *reinterpret_cast<unsigned*>(&t);
}
__device__ __forceinline__ void mma_bf16(float* c,
    unsigned a0, unsigned a1, unsigned a2, unsigned a3,
    unsigned b0, unsigned b1)
{
    asm volatile(
        "mma.sync.aligned.m16n8k16.row.col.f32.bf16.bf16.f32 "
        "{%0,%1,%2,%3},{%4,%5,%6,%7},{%8,%9},{%0,%1,%2,%3};\n"
        : "+f"(c[0]), "+f"(c[1]), "+f"(c[2]), "+f"(c[3])
        : "r"(a0), "r"(a1), "r"(a2), "r"(a3), "r"(b0), "r"(b1));
}
__device__ __forceinline__ uint32_t s2u(const void* p) {
    return (uint32_t)__cvta_generic_to_shared(p);
}
__device__ __forceinline__ void ldsm_x4(unsigned &r0, unsigned &r1,
                                        unsigned &r2, unsigned &r3, uint32_t a)
{
    asm volatile("ldmatrix.sync.aligned.m8n8.x4.shared.b16 {%0,%1,%2,%3}, [%4];"
        : "=r"(r0), "=r"(r1), "=r"(r2), "=r"(r3) : "r"(a));
}
// Fast 2^t (FMA pipe only), max rel err ~8e-6
__device__ __forceinline__ float fexp2(float t) {
    t = fmaxf(t, -125.0f);
    float fi = floorf(t);
    float f  = t - fi;
    float p  = 1.5403530e-4f;
    p = fmaf(p, f, 1.3333558e-3f);
    p = fmaf(p, f, 9.6181291e-3f);
    p = fmaf(p, f, 5.5504109e-2f);
    p = fmaf(p, f, 2.4022651e-1f);
    p = fmaf(p, f, 6.9314718e-1f);
    p = fmaf(p, f, 1.0f);
    return p * __int_as_float(((int)fi + 127) << 23);
}

// ---------------------------------------------------------------------------
// Tensor-core GEMM: on-the-fly fp32 -> hi/lo bf16 split, 3-pass MMA,
// ldmatrix frags, DOUBLE-BUFFERED smem (k-chunk 16, ONE sync per iter).
// CTA 128m x 64n, 8 warps (4m x 2n), warp 32x32.
// MODE 0: QKV -> scatter hi/lo bf16 (q,k natural; v transposed [d][t])
// MODE 1: proj -> fp32 d_out
// ---------------------------------------------------------------------------
#define ASTRIDE 24    // bf16; 48 B rows, ldsm slots 3r mod 8 all-distinct
#define A_BUF_BYTES (128*ASTRIDE*2)
#define B_BUF_BYTES (64*ASTRIDE*2)

template <int MODE>
__global__ void __launch_bounds__(256, 2)
mma_gemm(const float* __restrict__ A_g, const float* __restrict__ Bm,
         const float* __restrict__ bias, float* __restrict__ Cout, int Ncols)
{
    __shared__ __align__(16) bf16 Ash[2][128][ASTRIDE], Asl[2][128][ASTRIDE];
    __shared__ __align__(16) bf16 Bsh[2][64][ASTRIDE],  Bsl[2][64][ASTRIDE];

    const float* A = (MODE == 0) ? A_g : g_attn;
    const int tid = threadIdx.x;
    const int m0  = blockIdx.y * 128;
    const int n0  = blockIdx.x * 64;
    const int w   = tid >> 5, lane = tid & 31;
    const int wm  = w >> 1,  wn  = w & 1;
    const int g   = lane >> 2, t = lane & 3;

    const int bn  = tid & 63;      // B-fill: n within tile
    const int bkh = tid >> 6;      // B-fill: k-quad 0..3

    // ldmatrix lane-addressing (buffer 0 bases; add buf*BYTES)
    const int aRow = wm * 32 + (lane & 15);
    const int aCol = (lane & 16) >> 1;                 // 0 or 8
    const int bRow = wn * 32 + ((lane & 16) >> 1) + (lane & 7);
    const int bCol = lane & 8;                         // 0 or 8
    const uint32_t aBaseH = s2u(&Ash[0][aRow][aCol]);
    const uint32_t aBaseL = s2u(&Asl[0][aRow][aCol]);
    const uint32_t bBaseH = s2u(&Bsh[0][bRow][bCol]);
    const uint32_t bBaseL = s2u(&Bsl[0][bRow][bCol]);

    float C[2][4][4];
#pragma unroll
    for (int mf = 0; mf < 2; mf++)
#pragma unroll
        for (int nf = 0; nf < 4; nf++)
#pragma unroll
            for (int r = 0; r < 4; r++) C[mf][nf][r] = 0.f;

    float4 a_pf[2];
    float  b_pf[4];

    auto load_tile = [&](int k0) {
#pragma unroll
        for (int p = 0; p < 2; p++) {
            int id = tid + p * 256;                 // 0..511
            int r  = id >> 2, c4 = id & 3;          // 4 float4 cols of 16
            a_pf[p] = *(const float4*)(A + (size_t)(m0 + r) * KDIM + k0 + c4 * 4);
        }
#pragma unroll
        for (int kk = 0; kk < 4; kk++)
            b_pf[kk] = Bm[(size_t)(k0 + bkh * 4 + kk) * Ncols + n0 + bn];
    };
    auto store_tile = [&](int buf) {
#pragma unroll
        for (int p = 0; p < 2; p++) {
            int id = tid + p * 256;
            int r  = id >> 2, c4 = id & 3;
            bf16 h0,l0,h1,l1,h2,l2,h3,l3;
            bsplit(a_pf[p].x,h0,l0); bsplit(a_pf[p].y,h1,l1);
            bsplit(a_pf[p].z,h2,l2); bsplit(a_pf[p].w,h3,l3);
            *reinterpret_cast<uint2*>(&Ash[buf][r][c4*4]) = make_uint2(packb(h0,h1), packb(h2,h3));
            *reinterpret_cast<uint2*>(&Asl[buf][r][c4*4]) = make_uint2(packb(l0,l1), packb(l2,l3));
        }
        bf16 h0,l0,h1,l1,h2,l2,h3,l3;
        bsplit(b_pf[0],h0,l0); bsplit(b_pf[1],h1,l1);
        bsplit(b_pf[2],h2,l2); bsplit(b_pf[3],h3,l3);
        *reinterpret_cast<unsigned*>(&Bsh[buf][bn][bkh*4    ]) = packb(h0,h1);
        *reinterpret_cast<unsigned*>(&Bsh[buf][bn][bkh*4 + 2]) = packb(h2,h3);
        *reinterpret_cast<unsigned*>(&Bsl[buf][bn][bkh*4    ]) = packb(l0,l1);
        *reinterpret_cast<unsigned*>(&Bsl[buf][bn][bkh*4 + 2]) = packb(l2,l3);
    };

    load_tile(0);
    store_tile(0);
    __syncthreads();

    int cur = 0;
    for (int k0 = 0; k0 < KDIM; k0 += 16) {
        const bool has_next = (k0 + 16 < KDIM);
        if (has_next) load_tile(k0 + 16);     // global loads overlap MMAs

        const uint32_t aOff = (uint32_t)cur * A_BUF_BYTES;
        const uint32_t bOff = (uint32_t)cur * B_BUF_BYTES;
        unsigned ah[2][4], al[2][4];
#pragma unroll
        for (int mf = 0; mf < 2; mf++) {
            const uint32_t mOff = (uint32_t)(mf * 16 * ASTRIDE * 2);
            ldsm_x4(ah[mf][0], ah[mf][1], ah[mf][2], ah[mf][3], aBaseH + aOff + mOff);
            ldsm_x4(al[mf][0], al[mf][1], al[mf][2], al[mf][3], aBaseL + aOff + mOff);
        }
        unsigned bh[4][2], bl[4][2];
#pragma unroll
        for (int nfp = 0; nfp < 2; nfp++) {
            const uint32_t nOff = (uint32_t)(nfp * 16 * ASTRIDE * 2);
            ldsm_x4(bh[nfp*2][0], bh[nfp*2][1], bh[nfp*2+1][0], bh[nfp*2+1][1],
                    bBaseH + bOff + nOff);
            ldsm_x4(bl[nfp*2][0], bl[nfp*2][1], bl[nfp*2+1][0], bl[nfp*2+1][1],
                    bBaseL + bOff + nOff);
        }
#pragma unroll
        for (int nf = 0; nf < 4; nf++)
#pragma unroll
            for (int mf = 0; mf < 2; mf++) {
                mma_bf16(C[mf][nf], ah[mf][0],ah[mf][1],ah[mf][2],ah[mf][3],
                         bh[nf][0], bh[nf][1]);
                mma_bf16(C[mf][nf], ah[mf][0],ah[mf][1],ah[mf][2],ah[mf][3],
                         bl[nf][0], bl[nf][1]);
                mma_bf16(C[mf][nf], al[mf][0],al[mf][1],al[mf][2],al[mf][3],
                         bh[nf][0], bh[nf][1]);
            }

        if (has_next) store_tile(cur ^ 1);    // write OTHER buffer — no race
        __syncthreads();                      // one sync per iter
        cur ^= 1;
    }

    // Epilogue
#pragma unroll
    for (int mf = 0; mf < 2; mf++) {
#pragma unroll
        for (int nf = 0; nf < 4; nf++) {
            int n  = n0 + wn * 32 + nf * 8 + 2 * t;
            float b0 = bias[n], b1 = bias[n + 1];
            int mA = m0 + wm * 32 + mf * 16 + g;
            int mB = mA + 8;
            float v00 = C[mf][nf][0] + b0, v01 = C[mf][nf][1] + b1;
            float v10 = C[mf][nf][2] + b0, v11 = C[mf][nf][3] + b1;
            if (MODE == 0) {
                int s = n >> 10, h = (n >> 6) & 15, d = n & 63;
                int bhA = (mA >> 11) * HH + h, tA = mA & 2047;
                int bhB = (mB >> 11) * HH + h, tB = mB & 2047;
                bf16 h00,l00,h01,l01,h10,l10,h11,l11;
                bsplit(v00,h00,l00); bsplit(v01,h01,l01);
                bsplit(v10,h10,l10); bsplit(v11,h11,l11);
                if (s == 2) {
                    size_t iA0 = ((size_t)bhA * HD_ + d    ) * TT + tA;
                    size_t iA1 = ((size_t)bhA * HD_ + d + 1) * TT + tA;
                    size_t iB0 = ((size_t)bhB * HD_ + d    ) * TT + tB;
                    size_t iB1 = ((size_t)bhB * HD_ + d + 1) * TT + tB;
                    g_vth[iA0] = h00; g_vtl[iA0] = l00;
                    g_vth[iA1] = h01; g_vtl[iA1] = l01;
                    g_vth[iB0] = h10; g_vtl[iB0] = l10;
                    g_vth[iB1] = h11; g_vtl[iB1] = l11;
                } else {
                    bf16* ph = (s == 0) ? g_qh : g_kh;
                    bf16* pl = (s == 0) ? g_ql : g_kl;
                    size_t iA = ((size_t)bhA * TT + tA) * HD_ + d;
                    size_t iB = ((size_t)bhB * TT + tB) * HD_ + d;
                    *reinterpret_cast<unsigned*>(ph + iA) = packb(h00, h01);
                    *reinterpret_cast<unsigned*>(pl + iA) = packb(l00, l01);
                    *reinterpret_cast<unsigned*>(ph + iB) = packb(h10, h11);
                    *reinterpret_cast<unsigned*>(pl + iB) = packb(l10, l11);
                }
            } else {
                *reinterpret_cast<float2*>(&Cout[(size_t)mA * Ncols + n]) = make_float2(v00, v01);
                *reinterpret_cast<float2*>(&Cout[(size_t)mB * Ncols + n]) = make_float2(v10, v11);
            }
        }
    }
}

// ---------------------------------------------------------------------------
// Row norms from hi/lo bf16 q,k — one warp per (b,h,t) row  (proven)
// ---------------------------------------------------------------------------
__global__ void norms_kernel()
{
    int w    = (blockIdx.x * blockDim.x + threadIdx.x) >> 5;
    int lane = threadIdx.x & 31;
    size_t o = (size_t)w * HD_ + lane * 2;
    bf162 qh = *reinterpret_cast<bf162*>(g_qh + o);
    bf162 ql = *reinterpret_cast<bf162*>(g_ql + o);
    bf162 kh = *reinterpret_cast<bf162*>(g_kh + o);
    bf162 kl = *reinterpret_cast<bf162*>(g_kl + o);
    float q0 = __bfloat162float(qh.x) + __bfloat162float(ql.x);
    float q1 = __bfloat162float(qh.y) + __bfloat162float(ql.y);
    float k0 = __bfloat162float(kh.x) + __bfloat162float(kl.x);
    float k1 = __bfloat162float(kh.y) + __bfloat162float(kl.y);
    float sq = q0*q0 + q1*q1;
    float sk = k0*k0 + k1*k1;
#pragma unroll
    for (int off = 16; off; off >>= 1) {
        sq += __shfl_xor_sync(0xFFFFFFFFu, sq, off);
        sk += __shfl_xor_sync(0xFFFFFFFFu, sk, off);
    }
    if (lane == 0) { g_qn[w] = sq; g_kn[w] = sk; }
}

// ---------------------------------------------------------------------------
// Attention: K A-fragments hoisted to registers (j-loop-invariant), K smem
// aliased as the V buffer. 2 syncs per j-iter; Q+V loads batched.
// ---------------------------------------------------------------------------
__global__ void __launch_bounds__(128)
attn_mma_kernel(const float* __restrict__ sigp)
{
    __shared__ __align__(16) bf16 Vsh[64][72], Vsl[64][72];   // K tile first, then V
    __shared__ __align__(16) bf16 Qsh[64][72], Qsl[64][72];
    __shared__ float qns[64];

    const int tid  = threadIdx.x;
    const int w    = tid >> 5, lane = tid & 31;
    const int g    = lane >> 2, t = lane & 3;
    const int bh   = blockIdx.y;
    const int i0   = blockIdx.x * 64;
    const size_t base = (size_t)bh * TT * HD_;

    const float sigma = *sigp;
    const float c1    = -sigma * 1.4426950408889634f;
    const float m2c1  = -2.0f * c1;

    // Load K tile into (future V) smem
#pragma unroll
    for (int p = 0; p < 4; p++) {
        int id = tid + p * 128;
        int r  = id >> 3, qd = id & 7;
        size_t off = base + (size_t)(i0 + r) * HD_ + qd * 8;
        *reinterpret_cast<uint4*>(&Vsh[r][qd*8]) = *reinterpret_cast<const uint4*>(g_kh + off);
        *reinterpret_cast<uint4*>(&Vsl[r][qd*8]) = *reinterpret_cast<const uint4*>(g_kl + off);
    }
    __syncthreads();

    // Hoist K A-fragments (loop-invariant) into registers
    unsigned Kah[4][4], Kal[4][4];
#pragma unroll
    for (int kf = 0; kf < 4; kf++) {
        const int row = 16 * w;
        const int c0  = kf * 16 + 2 * t;
        Kah[kf][0] = *reinterpret_cast<unsigned*>(&Vsh[row+g  ][c0  ]);
        Kah[kf][1] = *reinterpret_cast<unsigned*>(&Vsh[row+g+8][c0  ]);
        Kah[kf][2] = *reinterpret_cast<unsigned*>(&Vsh[row+g  ][c0+8]);
        Kah[kf][3] = *reinterpret_cast<unsigned*>(&Vsh[row+g+8][c0+8]);
        Kal[kf][0] = *reinterpret_cast<unsigned*>(&Vsl[row+g  ][c0  ]);
        Kal[kf][1] = *reinterpret_cast<unsigned*>(&Vsl[row+g+8][c0  ]);
        Kal[kf][2] = *reinterpret_cast<unsigned*>(&Vsl[row+g  ][c0+8]);
        Kal[kf][3] = *reinterpret_cast<unsigned*>(&Vsl[row+g+8][c0+8]);
    }
    const float knc0 = c1 * g_kn[bh * TT + i0 + 16*w + g];
    const float knc8 = c1 * g_kn[bh * TT + i0 + 16*w + 8 + g];

    float O[8][4];
#pragma unroll
    for (int nf = 0; nf < 8; nf++)
#pragma unroll
        for (int r = 0; r < 4; r++) O[nf][r] = 0.f;

    for (int j0 = 0; j0 < TT; j0 += 64) {
        __syncthreads();   // K frags read (iter 0) / prev PV done reading Vs
        // Batched Q + V fills (coalesced; V pre-transposed [d][t] in global)
#pragma unroll
        for (int p = 0; p < 4; p++) {
            int id = tid + p * 128;
            int r  = id >> 3, qd = id & 7;
            size_t qoff = base + (size_t)(j0 + r) * HD_ + qd * 8;
            size_t voff = base + (size_t)r * TT + j0 + qd * 8;
            *reinterpret_cast<uint4*>(&Qsh[r][qd*8]) = *reinterpret_cast<const uint4*>(g_qh + qoff);
            *reinterpret_cast<uint4*>(&Qsl[r][qd*8]) = *reinterpret_cast<const uint4*>(g_ql + qoff);
            *reinterpret_cast<uint4*>(&Vsh[r][qd*8]) = *reinterpret_cast<const uint4*>(g_vth + voff);
            *reinterpret_cast<uint4*>(&Vsl[r][qd*8]) = *reinterpret_cast<const uint4*>(g_vtl + voff);
        }
        if (tid < 64) qns[tid] = c1 * g_qn[bh * TT + j0 + tid];
        __syncthreads();

        // S = K·Q^T (K frags in regs)
        float S[8][4];
#pragma unroll
        for (int nf = 0; nf < 8; nf++)
#pragma unroll
            for (int r = 0; r < 4; r++) S[nf][r] = 0.f;
#pragma unroll
        for (int kf = 0; kf < 4; kf++) {
            const int c0 = kf * 16 + 2 * t;
#pragma unroll
            for (int nf = 0; nf < 8; nf++) {
                unsigned bh0 = *reinterpret_cast<unsigned*>(&Qsh[nf*8+g][c0  ]);
                unsigned bh1 = *reinterpret_cast<unsigned*>(&Qsh[nf*8+g][c0+8]);
                unsigned bl0 = *reinterpret_cast<unsigned*>(&Qsl[nf*8+g][c0  ]);
                unsigned bl1 = *reinterpret_cast<unsigned*>(&Qsl[nf*8+g][c0+8]);
                mma_bf16(S[nf], Kah[kf][0],Kah[kf][1],Kah[kf][2],Kah[kf][3], bh0, bh1);
                mma_bf16(S[nf], Kah[kf][0],Kah[kf][1],Kah[kf][2],Kah[kf][3], bl0, bl1);
                mma_bf16(S[nf], Kal[kf][0],Kal[kf][1],Kal[kf][2],Kal[kf][3], bh0, bh1);
            }
        }

        // P = exp kernel; repack S C-frags -> PV A-frags (in-thread)
        unsigned Ph[4][4], Pl[4][4];
#pragma unroll
        for (int nf = 0; nf < 8; nf++) {
            float qn0 = qns[nf*8 + 2*t], qn1 = qns[nf*8 + 2*t + 1];
            float p00 = fexp2(fmaf(m2c1, S[nf][0], knc0 + qn0));
            float p01 = fexp2(fmaf(m2c1, S[nf][1], knc0 + qn1));
            float p10 = fexp2(fmaf(m2c1, S[nf][2], knc8 + qn0));
            float p11 = fexp2(fmaf(m2c1, S[nf][3], knc8 + qn1));
            bf16 h00,l00,h01,l01,h10,l10,h11,l11;
            bsplit(p00,h00,l00); bsplit(p01,h01,l01);
            bsplit(p10,h10,l10); bsplit(p11,h11,l11);
            int kf = nf >> 1;
            if ((nf & 1) == 0) {
                Ph[kf][0] = packb(h00,h01); Ph[kf][1] = packb(h10,h11);
                Pl[kf][0] = packb(l00,l01); Pl[kf][1] = packb(l10,l11);
            } else {
                Ph[kf][2] = packb(h00,h01); Ph[kf][3] = packb(h10,h11);
                Pl[kf][2] = packb(l00,l01); Pl[kf][3] = packb(l10,l11);
            }
        }

        // O += P @ V  (V already resident in Vsh/Vsl — no extra sync)
#pragma unroll
        for (int kf = 0; kf < 4; kf++) {
            const int jc = kf * 8 + t;
#pragma unroll
            for (int nf = 0; nf < 8; nf++) {
                const unsigned* rowh = reinterpret_cast<const unsigned*>(&Vsh[nf*8+g][0]);
                const unsigned* rowl = reinterpret_cast<const unsigned*>(&Vsl[nf*8+g][0]);
                unsigned bh0 = rowh[jc];
                unsigned bh1 = rowh[jc + 4];
                unsigned bl0 = rowl[jc];
                unsigned bl1 = rowl[jc + 4];
                mma_bf16(O[nf], Ph[kf][0],Ph[kf][1],Ph[kf][2],Ph[kf][3], bh0, bh1);
                mma_bf16(O[nf], Ph[kf][0],Ph[kf][1],Ph[kf][2],Ph[kf][3], bl0, bl1);
                mma_bf16(O[nf], Pl[kf][0],Pl[kf][1],Pl[kf][2],Pl[kf][3], bh0, bh1);
            }
        }
    }

    const int b_ = bh >> 4;
    const int h  = bh & 15;
#pragma unroll
    for (int nf = 0; nf < 8; nf++) {
        int d  = nf * 8 + 2 * t;
        int iA = i0 + 16*w + g;
        int iB = iA + 8;
        size_t oA = ((size_t)b_ * TT + iA) * DIM_ + h * HD_ + d;
        size_t oB = ((size_t)b_ * TT + iB) * DIM_ + h * HD_ + d;
        *reinterpret_cast<float2*>(g_attn + oA) = make_float2(O[nf][0], O[nf][1]);
        *reinterpret_cast<float2*>(g_attn + oB) = make_float2(O[nf][2], O[nf][3]);
    }
}

// ---------------------------------------------------------------------------
// kernel_launch — inputs: x, Wqkv, bqkv, r_sigma, Wproj, bproj
// ---------------------------------------------------------------------------
extern "C" void kernel_launch(void* const* d_in, const int* in_sizes, int n_in,
                              void* d_out, int out_size)
{
    (void)in_sizes; (void)n_in; (void)out_size;
    const float* x     = (const float*)d_in[0];
    const float* Wqkv  = (const float*)d_in[1];
    const float* bqkv  = (const float*)d_in[2];
    const float* sig   = (const float*)d_in[3];
    const float* Wproj = (const float*)d_in[4];
    const float* bproj = (const float*)d_in[5];
    float* out = (float*)d_out;

    mma_gemm<0><<<dim3(N1/64, M1/128), 256>>>(x, Wqkv, bqkv, nullptr, N1);
    norms_kernel<<<(NROWS * 32) / 256, 256>>>();
    attn_mma_kernel<<<dim3(TT/64, BB*HH), 128>>>(sig);
    mma_gemm<1><<<dim3(CC/64, M1/128), 256>>>(nullptr, Wproj, bproj, out, CC);
}

// round 13
// speedup vs baseline: 1.2159x; 1.2159x over previous
#include <cuda_runtime.h>
#include <cuda_bf16.h>
#include <cstdint>
#include <cstddef>

#define BB   2
#define TT   2048
#define CC   1024
#define DIM_ 1024
#define HH   16
#define HD_  64
#define M1   (BB*TT)        // 4096
#define N1   (3*DIM_)       // 3072
#define KDIM 1024
#define NROWS (BB*HH*TT)    // 65536

typedef __nv_bfloat16  bf16;
typedef __nv_bfloat162 bf162;

// ---------------------------------------------------------------------------
// Scratch — EXACTLY 64.5 MiB (proven footprint). No other globals.
// ---------------------------------------------------------------------------
__device__ __align__(16) bf16 g_qh[(size_t)NROWS*HD_], g_ql[(size_t)NROWS*HD_];
__device__ __align__(16) bf16 g_kh[(size_t)NROWS*HD_], g_kl[(size_t)NROWS*HD_];
__device__ __align__(16) bf16 g_vth[(size_t)NROWS*HD_], g_vtl[(size_t)NROWS*HD_];
__device__ float g_attn[(size_t)M1*DIM_];
__device__ float g_qn[NROWS], g_kn[NROWS];

// ---------------------------------------------------------------------------
// Helpers
// ---------------------------------------------------------------------------
__device__ __forceinline__ void bsplit(float x, bf16 &h, bf16 &l) {
    h = __float2bfloat16_rn(x);
    l = __float2bfloat16_rn(x - __bfloat162float(h));
}
__device__ __forceinline__ unsigned packb(bf16 a, bf16 b) {
    bf162 t; t.x = a; t.y = b;
    return *reinterpret_cast<unsigned*>(&t);
}
__device__ __forceinline__ void mma_bf16(float* c,
    unsigned a0, unsigned a1, unsigned a2, unsigned a3,
    unsigned b0, unsigned b1)
{
    asm volatile(
        "mma.sync.aligned.m16n8k16.row.col.f32.bf16.bf16.f32 "
        "{%0,%1,%2,%3},{%4,%5,%6,%7},{%8,%9},{%0,%1,%2,%3};\n"
        : "+f"(c[0]), "+f"(c[1]), "+f"(c[2]), "+f"(c[3])
        : "r"(a0), "r"(a1), "r"(a2), "r"(a3), "r"(b0), "r"(b1));
}
__device__ __forceinline__ uint32_t s2u(const void* p) {
    return (uint32_t)__cvta_generic_to_shared(p);
}
__device__ __forceinline__ void ldsm_x4(unsigned &r0, unsigned &r1,
                                        unsigned &r2, unsigned &r3, uint32_t a)
{
    asm volatile("ldmatrix.sync.aligned.m8n8.x4.shared.b16 {%0,%1,%2,%3}, [%4];"
        : "=r"(r0), "=r"(r1), "=r"(r2), "=r"(r3) : "r"(a));
}
// Fast 2^t (FMA pipe only), max rel err ~8e-6
__device__ __forceinline__ float fexp2(float t) {
    t = fmaxf(t, -125.0f);
    float fi = floorf(t);
    float f  = t - fi;
    float p  = 1.5403530e-4f;
    p = fmaf(p, f, 1.3333558e-3f);
    p = fmaf(p, f, 9.6181291e-3f);
    p = fmaf(p, f, 5.5504109e-2f);
    p = fmaf(p, f, 2.4022651e-1f);
    p = fmaf(p, f, 6.9314718e-1f);
    p = fmaf(p, f, 1.0f);
    return p * __int_as_float(((int)fi + 127) << 23);
}

// ---------------------------------------------------------------------------
// Tensor-core GEMM (round-9 proven, verbatim): on-the-fly fp32 -> hi/lo bf16
// split, 3-pass MMA, ldmatrix frags, register-prefetch pipeline, k-chunk 32.
// CTA 128m x 64n, 8 warps (4m x 2n), warp 32x32.
// MODE 0: QKV -> scatter hi/lo bf16 (q,k natural; v transposed [d][t])
// MODE 1: proj -> fp32 d_out
// ---------------------------------------------------------------------------
template <int MODE>
__global__ void __launch_bounds__(256, 2)
mma_gemm(const float* __restrict__ A_g, const float* __restrict__ Bm,
         const float* __restrict__ bias, float* __restrict__ Cout, int Ncols)
{
    __shared__ __align__(16) bf16 Ash[128][40], Asl[128][40];
    __shared__ __align__(16) bf16 Bsh[64][40],  Bsl[64][40];

    const float* A = (MODE == 0) ? A_g : g_attn;
    const int tid = threadIdx.x;
    const int m0  = blockIdx.y * 128;
    const int n0  = blockIdx.x * 64;
    const int w   = tid >> 5, lane = tid & 31;
    const int wm  = w >> 1,  wn  = w & 1;
    const int g   = lane >> 2, t = lane & 3;

    const int bn  = tid & 63;      // B-fill: n within tile
    const int bkh = tid >> 6;      // B-fill: k-octet 0..3

    // ldmatrix lane-addressing (constant per thread)
    const int aRow = wm * 32 + (lane & 15);
    const int aCol = (lane & 16) >> 1;                 // 0 or 8
    const int bRow = wn * 32 + ((lane & 16) >> 1) + (lane & 7);
    const int bCol = lane & 8;                         // 0 or 8
    const uint32_t aBaseH = s2u(&Ash[aRow][aCol]);
    const uint32_t aBaseL = s2u(&Asl[aRow][aCol]);
    const uint32_t bBaseH = s2u(&Bsh[bRow][bCol]);
    const uint32_t bBaseL = s2u(&Bsl[bRow][bCol]);

    float C[2][4][4];
#pragma unroll
    for (int mf = 0; mf < 2; mf++)
#pragma unroll
        for (int nf = 0; nf < 4; nf++)
#pragma unroll
            for (int r = 0; r < 4; r++) C[mf][nf][r] = 0.f;

    float4 a_pf[4];
    float  b_pf[8];

    auto load_tile = [&](int k0) {
#pragma unroll
        for (int p = 0; p < 4; p++) {
            int id = tid + p * 256;
            int r  = id >> 3, c4 = id & 7;
            a_pf[p] = *(const float4*)(A + (size_t)(m0 + r) * KDIM + k0 + c4 * 4);
        }
#pragma unroll
        for (int kk2 = 0; kk2 < 4; kk2++) {
            int k = bkh * 8 + kk2 * 2;
            b_pf[kk2*2  ] = Bm[(size_t)(k0 + k    ) * Ncols + n0 + bn];
            b_pf[kk2*2+1] = Bm[(size_t)(k0 + k + 1) * Ncols + n0 + bn];
        }
    };
    auto store_tile = [&]() {
#pragma unroll
        for (int p = 0; p < 4; p++) {
            int id = tid + p * 256;
            int r  = id >> 3, c4 = id & 7;
            bf16 h0,l0,h1,l1,h2,l2,h3,l3;
            bsplit(a_pf[p].x,h0,l0); bsplit(a_pf[p].y,h1,l1);
            bsplit(a_pf[p].z,h2,l2); bsplit(a_pf[p].w,h3,l3);
            *reinterpret_cast<uint2*>(&Ash[r][c4*4]) = make_uint2(packb(h0,h1), packb(h2,h3));
            *reinterpret_cast<uint2*>(&Asl[r][c4*4]) = make_uint2(packb(l0,l1), packb(l2,l3));
        }
#pragma unroll
        for (int kk2 = 0; kk2 < 4; kk2++) {
            int k = bkh * 8 + kk2 * 2;
            bf16 h0,l0,h1,l1;
            bsplit(b_pf[kk2*2  ],h0,l0); bsplit(b_pf[kk2*2+1],h1,l1);
            *reinterpret_cast<unsigned*>(&Bsh[bn][k]) = packb(h0,h1);
            *reinterpret_cast<unsigned*>(&Bsl[bn][k]) = packb(l0,l1);
        }
    };

    load_tile(0);
    store_tile();
    __syncthreads();

    for (int k0 = 0; k0 < KDIM; k0 += 32) {
        const bool has_next = (k0 + 32 < KDIM);
        if (has_next) load_tile(k0 + 32);   // global loads overlap the MMAs below

#pragma unroll
        for (int ks = 0; ks < 2; ks++) {
            const uint32_t ksOff = (uint32_t)(ks * 16 * 2);   // bytes
            unsigned ah[2][4], al[2][4];
#pragma unroll
            for (int mf = 0; mf < 2; mf++) {
                const uint32_t mOff = (uint32_t)(mf * 16 * 40 * 2);
                ldsm_x4(ah[mf][0], ah[mf][1], ah[mf][2], ah[mf][3], aBaseH + mOff + ksOff);
                ldsm_x4(al[mf][0], al[mf][1], al[mf][2], al[mf][3], aBaseL + mOff + ksOff);
            }
            unsigned bh[4][2], bl[4][2];
#pragma unroll
            for (int nfp = 0; nfp < 2; nfp++) {
                const uint32_t nOff = (uint32_t)(nfp * 16 * 40 * 2);
                ldsm_x4(bh[nfp*2][0], bh[nfp*2][1], bh[nfp*2+1][0], bh[nfp*2+1][1],
                        bBaseH + nOff + ksOff);
                ldsm_x4(bl[nfp*2][0], bl[nfp*2][1], bl[nfp*2+1][0], bl[nfp*2+1][1],
                        bBaseL + nOff + ksOff);
            }
#pragma unroll
            for (int nf = 0; nf < 4; nf++)
#pragma unroll
                for (int mf = 0; mf < 2; mf++) {
                    mma_bf16(C[mf][nf], ah[mf][0],ah[mf][1],ah[mf][2],ah[mf][3],
                             bh[nf][0], bh[nf][1]);
                    mma_bf16(C[mf][nf], ah[mf][0],ah[mf][1],ah[mf][2],ah[mf][3],
                             bl[nf][0], bl[nf][1]);
                    mma_bf16(C[mf][nf], al[mf][0],al[mf][1],al[mf][2],al[mf][3],
                             bh[nf][0], bh[nf][1]);
                }
        }

        if (has_next) {
            __syncthreads();        // everyone done reading current tile
            store_tile();
            __syncthreads();        // next tile visible
        }
    }

    // Epilogue
#pragma unroll
    for (int mf = 0; mf < 2; mf++) {
#pragma unroll
        for (int nf = 0; nf < 4; nf++) {
            int n  = n0 + wn * 32 + nf * 8 + 2 * t;
            float b0 = bias[n], b1 = bias[n + 1];
            int mA = m0 + wm * 32 + mf * 16 + g;
            int mB = mA + 8;
            float v00 = C[mf][nf][0] + b0, v01 = C[mf][nf][1] + b1;
            float v10 = C[mf][nf][2] + b0, v11 = C[mf][nf][3] + b1;
            if (MODE == 0) {
                int s = n >> 10, h = (n >> 6) & 15, d = n & 63;
                int bhA = (mA >> 11) * HH + h, tA = mA & 2047;
                int bhB = (mB >> 11) * HH + h, tB = mB & 2047;
                bf16 h00,l00,h01,l01,h10,l10,h11,l11;
                bsplit(v00,h00,l00); bsplit(v01,h01,l01);
                bsplit(v10,h10,l10); bsplit(v11,h11,l11);
                if (s == 2) {
                    size_t iA0 = ((size_t)bhA * HD_ + d    ) * TT + tA;
                    size_t iA1 = ((size_t)bhA * HD_ + d + 1) * TT + tA;
                    size_t iB0 = ((size_t)bhB * HD_ + d    ) * TT + tB;
                    size_t iB1 = ((size_t)bhB * HD_ + d + 1) * TT + tB;
                    g_vth[iA0] = h00; g_vtl[iA0] = l00;
                    g_vth[iA1] = h01; g_vtl[iA1] = l01;
                    g_vth[iB0] = h10; g_vtl[iB0] = l10;
                    g_vth[iB1] = h11; g_vtl[iB1] = l11;
                } else {
                    bf16* ph = (s == 0) ? g_qh : g_kh;
                    bf16* pl = (s == 0) ? g_ql : g_kl;
                    size_t iA = ((size_t)bhA * TT + tA) * HD_ + d;
                    size_t iB = ((size_t)bhB * TT + tB) * HD_ + d;
                    *reinterpret_cast<unsigned*>(ph + iA) = packb(h00, h01);
                    *reinterpret_cast<unsigned*>(pl + iA) = packb(l00, l01);
                    *reinterpret_cast<unsigned*>(ph + iB) = packb(h10, h11);
                    *reinterpret_cast<unsigned*>(pl + iB) = packb(l10, l11);
                }
            } else {
                *reinterpret_cast<float2*>(&Cout[(size_t)mA * Ncols + n]) = make_float2(v00, v01);
                *reinterpret_cast<float2*>(&Cout[(size_t)mB * Ncols + n]) = make_float2(v10, v11);
            }
        }
    }
}

// ---------------------------------------------------------------------------
// Row norms from hi/lo bf16 q,k — one warp per (b,h,t) row  (proven)
// ---------------------------------------------------------------------------
__global__ void norms_kernel()
{
    int w    = (blockIdx.x * blockDim.x + threadIdx.x) >> 5;
    int lane = threadIdx.x & 31;
    size_t o = (size_t)w * HD_ + lane * 2;
    bf162 qh = *reinterpret_cast<bf162*>(g_qh + o);
    bf162 ql = *reinterpret_cast<bf162*>(g_ql + o);
    bf162 kh = *reinterpret_cast<bf162*>(g_kh + o);
    bf162 kl = *reinterpret_cast<bf162*>(g_kl + o);
    float q0 = __bfloat162float(qh.x) + __bfloat162float(ql.x);
    float q1 = __bfloat162float(qh.y) + __bfloat162float(ql.y);
    float k0 = __bfloat162float(kh.x) + __bfloat162float(kl.x);
    float k1 = __bfloat162float(kh.y) + __bfloat162float(kl.y);
    float sq = q0*q0 + q1*q1;
    float sk = k0*k0 + k1*k1;
#pragma unroll
    for (int off = 16; off; off >>= 1) {
        sq += __shfl_xor_sync(0xFFFFFFFFu, sq, off);
        sk += __shfl_xor_sync(0xFFFFFFFFu, sk, off);
    }
    if (lane == 0) { g_qn[w] = sq; g_kn[w] = sk; }
}

// ---------------------------------------------------------------------------
// Attention (round-9 structure, ONE change: scalar LDS fragment loads
// replaced with ldmatrix). CTA 128 thr, i-tile 64, j-tiles 64, 4 syncs/iter.
// K frags re-loaded per iter (NO hoisting — round-11 regression lesson).
// Stride 72 bf16 = 9 x 16B slots -> 9r mod 8 = r, ldsm conflict-free.
// ---------------------------------------------------------------------------
__global__ void __launch_bounds__(128)
attn_mma_kernel(const float* __restrict__ sigp)
{
    __shared__ __align__(16) bf16 Ksh[64][72], Ksl[64][72];
    __shared__ __align__(16) bf16 QVh[64][72], QVl[64][72];
    __shared__ float qns[64];

    const int tid  = threadIdx.x;
    const int w    = tid >> 5, lane = tid & 31;
    const int g    = lane >> 2, t = lane & 3;
    const int bh   = blockIdx.y;
    const int i0   = blockIdx.x * 64;
    const size_t base = (size_t)bh * TT * HD_;

    const float sigma = *sigp;
    const float c1    = -sigma * 1.4426950408889634f;
    const float m2c1  = -2.0f * c1;

    // ldmatrix lane-addressing
    const int aRow = 16 * w + (lane & 15);
    const int aCol = (lane & 16) >> 1;                 // 0 or 8
    const int bRow = ((lane & 16) >> 1) + (lane & 7);  // row within 16-block
    const int bCol = lane & 8;                         // 0 or 8
    const uint32_t kBaseH = s2u(&Ksh[aRow][aCol]);
    const uint32_t kBaseL = s2u(&Ksl[aRow][aCol]);
    const uint32_t qvBaseH = s2u(&QVh[bRow][bCol]);
    const uint32_t qvBaseL = s2u(&QVl[bRow][bCol]);

    // K tile (persistent): [i][d]
#pragma unroll
    for (int p = 0; p < 4; p++) {
        int id = tid + p * 128;
        int r  = id >> 3, qd = id & 7;
        size_t off = base + (size_t)(i0 + r) * HD_ + qd * 8;
        *reinterpret_cast<uint4*>(&Ksh[r][qd*8]) = *reinterpret_cast<const uint4*>(g_kh + off);
        *reinterpret_cast<uint4*>(&Ksl[r][qd*8]) = *reinterpret_cast<const uint4*>(g_kl + off);
    }
    const float knc0 = c1 * g_kn[bh * TT + i0 + 16*w + g];
    const float knc8 = c1 * g_kn[bh * TT + i0 + 16*w + 8 + g];

    float O[8][4];
#pragma unroll
    for (int nf = 0; nf < 8; nf++)
#pragma unroll
        for (int r = 0; r < 4; r++) O[nf][r] = 0.f;

    for (int j0 = 0; j0 < TT; j0 += 64) {
        __syncthreads();   // prev iter done reading QV (K visible first iter)
        // Q tile [j][d] — coalesced
#pragma unroll
        for (int p = 0; p < 4; p++) {
            int id = tid + p * 128;
            int r  = id >> 3, qd = id & 7;
            size_t off = base + (size_t)(j0 + r) * HD_ + qd * 8;
            *reinterpret_cast<uint4*>(&QVh[r][qd*8]) = *reinterpret_cast<const uint4*>(g_qh + off);
            *reinterpret_cast<uint4*>(&QVl[r][qd*8]) = *reinterpret_cast<const uint4*>(g_ql + off);
        }
        if (tid < 64) qns[tid] = c1 * g_qn[bh * TT + j0 + tid];
        __syncthreads();

        // S = K·Q^T  (A = K rows via ldsm, B = Q via ldsm; 3-pass hi/lo)
        float S[8][4];
#pragma unroll
        for (int nf = 0; nf < 8; nf++)
#pragma unroll
            for (int r = 0; r < 4; r++) S[nf][r] = 0.f;
#pragma unroll
        for (int kf = 0; kf < 4; kf++) {
            const uint32_t kOff = (uint32_t)(kf * 16 * 2);   // 16 bf16 cols
            unsigned ah0, ah1, ah2, ah3, al0, al1, al2, al3;
            ldsm_x4(ah0, ah1, ah2, ah3, kBaseH + kOff);
            ldsm_x4(al0, al1, al2, al3, kBaseL + kOff);
#pragma unroll
            for (int nfp = 0; nfp < 4; nfp++) {
                const uint32_t nOff = (uint32_t)(nfp * 16 * 72 * 2);
                unsigned bh0, bh1, bh2, bh3, bl0, bl1, bl2, bl3;
                ldsm_x4(bh0, bh1, bh2, bh3, qvBaseH + nOff + kOff);
                ldsm_x4(bl0, bl1, bl2, bl3, qvBaseL + nOff + kOff);
                mma_bf16(S[nfp*2  ], ah0, ah1, ah2, ah3, bh0, bh1);
                mma_bf16(S[nfp*2  ], ah0, ah1, ah2, ah3, bl0, bl1);
                mma_bf16(S[nfp*2  ], al0, al1, al2, al3, bh0, bh1);
                mma_bf16(S[nfp*2+1], ah0, ah1, ah2, ah3, bh2, bh3);
                mma_bf16(S[nfp*2+1], ah0, ah1, ah2, ah3, bl2, bl3);
                mma_bf16(S[nfp*2+1], al0, al1, al2, al3, bh2, bh3);
            }
        }

        // P = exp kernel; repack S C-frags -> PV A-frags (in-thread)
        unsigned Ph[4][4], Pl[4][4];
#pragma unroll
        for (int nf = 0; nf < 8; nf++) {
            float qn0 = qns[nf*8 + 2*t], qn1 = qns[nf*8 + 2*t + 1];
            float p00 = fexp2(fmaf(m2c1, S[nf][0], knc0 + qn0));
            float p01 = fexp2(fmaf(m2c1, S[nf][1], knc0 + qn1));
            float p10 = fexp2(fmaf(m2c1, S[nf][2], knc8 + qn0));
            float p11 = fexp2(fmaf(m2c1, S[nf][3], knc8 + qn1));
            bf16 h00,l00,h01,l01,h10,l10,h11,l11;
            bsplit(p00,h00,l00); bsplit(p01,h01,l01);
            bsplit(p10,h10,l10); bsplit(p11,h11,l11);
            int kf = nf >> 1;
            if ((nf & 1) == 0) {
                Ph[kf][0] = packb(h00,h01); Ph[kf][1] = packb(h10,h11);
                Pl[kf][0] = packb(l00,l01); Pl[kf][1] = packb(l10,l11);
            } else {
                Ph[kf][2] = packb(h00,h01); Ph[kf][3] = packb(h10,h11);
                Pl[kf][2] = packb(l00,l01); Pl[kf][3] = packb(l10,l11);
            }
        }
        __syncthreads();   // done reading Q from QV

        // V^T tile [d][j] — coalesced load from pre-transposed global
#pragma unroll
        for (int p = 0; p < 4; p++) {
            int id = tid + p * 128;
            int r  = id >> 3, qd = id & 7;
            size_t off = base + (size_t)r * TT + j0 + qd * 8;
            *reinterpret_cast<uint4*>(&QVh[r][qd*8]) = *reinterpret_cast<const uint4*>(g_vth + off);
            *reinterpret_cast<uint4*>(&QVl[r][qd*8]) = *reinterpret_cast<const uint4*>(g_vtl + off);
        }
        __syncthreads();

        // O += P @ V  (A = P regs; B = V^T[d][j] via ldsm: n=d, k=j)
#pragma unroll
        for (int kf = 0; kf < 4; kf++) {
            const uint32_t kOff = (uint32_t)(kf * 16 * 2);   // 16 j's
#pragma unroll
            for (int nfp = 0; nfp < 4; nfp++) {
                const uint32_t nOff = (uint32_t)(nfp * 16 * 72 * 2);
                unsigned bh0, bh1, bh2, bh3, bl0, bl1, bl2, bl3;
                ldsm_x4(bh0, bh1, bh2, bh3, qvBaseH + nOff + kOff);
                ldsm_x4(bl0, bl1, bl2, bl3, qvBaseL + nOff + kOff);
                mma_bf16(O[nfp*2  ], Ph[kf][0],Ph[kf][1],Ph[kf][2],Ph[kf][3], bh0, bh1);
                mma_bf16(O[nfp*2  ], Ph[kf][0],Ph[kf][1],Ph[kf][2],Ph[kf][3], bl0, bl1);
                mma_bf16(O[nfp*2  ], Pl[kf][0],Pl[kf][1],Pl[kf][2],Pl[kf][3], bh0, bh1);
                mma_bf16(O[nfp*2+1], Ph[kf][0],Ph[kf][1],Ph[kf][2],Ph[kf][3], bh2, bh3);
                mma_bf16(O[nfp*2+1], Ph[kf][0],Ph[kf][1],Ph[kf][2],Ph[kf][3], bl2, bl3);
                mma_bf16(O[nfp*2+1], Pl[kf][0],Pl[kf][1],Pl[kf][2],Pl[kf][3], bh2, bh3);
            }
        }
    }

    // Write fp32 attn-out in (B, T, DIM) layout
    const int b_ = bh >> 4;
    const int h  = bh & 15;
#pragma unroll
    for (int nf = 0; nf < 8; nf++) {
        int d  = nf * 8 + 2 * t;
        int iA = i0 + 16*w + g;
        int iB = iA + 8;
        size_t oA = ((size_t)b_ * TT + iA) * DIM_ + h * HD_ + d;
        size_t oB = ((size_t)b_ * TT + iB) * DIM_ + h * HD_ + d;
        *reinterpret_cast<float2*>(g_attn + oA) = make_float2(O[nf][0], O[nf][1]);
        *reinterpret_cast<float2*>(g_attn + oB) = make_float2(O[nf][2], O[nf][3]);
    }
}

// ---------------------------------------------------------------------------
// kernel_launch — inputs: x, Wqkv, bqkv, r_sigma, Wproj, bproj
// ---------------------------------------------------------------------------
extern "C" void kernel_launch(void* const* d_in, const int* in_sizes, int n_in,
                              void* d_out, int out_size)
{
    (void)in_sizes; (void)n_in; (void)out_size;
    const float* x     = (const float*)d_in[0];
    const float* Wqkv  = (const float*)d_in[1];
    const float* bqkv  = (const float*)d_in[2];
    const float* sig   = (const float*)d_in[3];
    const float* Wproj = (const float*)d_in[4];
    const float* bproj = (const float*)d_in[5];
    float* out = (float*)d_out;

    mma_gemm<0><<<dim3(N1/64, M1/128), 256>>>(x, Wqkv, bqkv, nullptr, N1);
    norms_kernel<<<(NROWS * 32) / 256, 256>>>();
    attn_mma_kernel<<<dim3(TT/64, BB*HH), 128>>>(sig);
    mma_gemm<1><<<dim3(CC/64, M1/128), 256>>>(nullptr, Wproj, bproj, out, CC);
}